// round 1
// baseline (speedup 1.0000x reference)
#include <cuda_runtime.h>
#include <cstdint>

// ScatterEdges: out[src[e]] += x[e]*switch[e]; out[dst[e]] += x[e]*switch[e]
// E = 3.2M edges, D = 64 features, N = 100K nodes.

#define D_FEAT 64
#define VECS_PER_EDGE 16   // 64 floats / float4

__global__ void zero_out_kernel(float4* __restrict__ out4, int n4) {
    int i = blockIdx.x * blockDim.x + threadIdx.x;
    int stride = gridDim.x * blockDim.x;
    for (; i < n4; i += stride) {
        out4[i] = make_float4(0.f, 0.f, 0.f, 0.f);
    }
}

__global__ void __launch_bounds__(256)
scatter_edges_kernel(const float4* __restrict__ x4,
                     const float* __restrict__ sw,
                     const int* __restrict__ src,
                     const int* __restrict__ dst,
                     float* __restrict__ out,
                     int n_edges) {
    int gid = blockIdx.x * blockDim.x + threadIdx.x;
    int lane16 = gid & (VECS_PER_EDGE - 1);   // which float4 within the row
    int e = gid >> 4;                          // edge index
    if (e >= n_edges) return;

    float s = __ldg(&sw[e]);
    int a = __ldg(&src[e]);
    int b = __ldg(&dst[e]);

    float4 v = __ldg(&x4[(size_t)e * VECS_PER_EDGE + lane16]);
    v.x *= s; v.y *= s; v.z *= s; v.w *= s;

    float* pa = out + (size_t)a * D_FEAT + lane16 * 4;
    float* pb = out + (size_t)b * D_FEAT + lane16 * 4;

    asm volatile("red.global.add.v4.f32 [%0], {%1, %2, %3, %4};"
                 :: "l"(pa), "f"(v.x), "f"(v.y), "f"(v.z), "f"(v.w)
                 : "memory");
    asm volatile("red.global.add.v4.f32 [%0], {%1, %2, %3, %4};"
                 :: "l"(pb), "f"(v.x), "f"(v.y), "f"(v.z), "f"(v.w)
                 : "memory");
}

extern "C" void kernel_launch(void* const* d_in, const int* in_sizes, int n_in,
                              void* d_out, int out_size) {
    // metadata order: x [E*64], switch [E], edge_src [E], edge_dst [E], species [N]
    const float4* x4  = (const float4*)d_in[0];
    const float*  sw  = (const float*)d_in[1];
    const int*    src = (const int*)d_in[2];
    const int*    dst = (const int*)d_in[3];
    float* out = (float*)d_out;

    int n_edges = in_sizes[1];   // switch has E elements

    // Zero the (poisoned) output first.
    int n4 = out_size / 4;
    int zblocks = (n4 + 255) / 256;
    if (zblocks > 8192) zblocks = 8192;
    zero_out_kernel<<<zblocks, 256>>>((float4*)out, n4);

    // One float4 lane-slot per (edge, 16B chunk).
    long long total_threads = (long long)n_edges * VECS_PER_EDGE;
    int blocks = (int)((total_threads + 255) / 256);
    scatter_edges_kernel<<<blocks, 256>>>(x4, sw, src, dst, out, n_edges);
}